// round 12
// baseline (speedup 1.0000x reference)
#include <cuda_runtime.h>
#include <cuda_fp16.h>
#include <stdint.h>
#include <math.h>

// B=64, I=2048, N=16, J=16, M=16, 3 routing iters
#define B_  64
#define I_  2048
#define N_  16
#define J_  16
#define M_  16
#define JM  256
#define WPC 8
#define C_  8                    // chunks (CTAs) per batch b
#define IPW (I_/(C_*WPC))        // = 32 i per warp per phase (4 batches of 8)

// Scratch (device globals). fp16 u_hat = 67 MB.
__device__ __half g_uhat[(size_t)B_ * I_ * JM];     // [b][i][j*16+m]
__device__ float  g_scratch[3 * B_ * JM];           // s per phase
__device__ float  g_osum[B_ * JM];
__device__ int    g_counters[3 * B_];
__device__ int    g_flag[B_];

// ---------------------------------------------------------------------------
// K1 (HMMA): per CTA = one input capsule i.  (unchanged from R8 baseline)
#define XPAD 18
#define WPAD 18
#define DPAD 264
__global__ void __launch_bounds__(256) k_uhat(const float* __restrict__ inp,
                                              const float* __restrict__ W) {
    __shared__ __half Xh[B_ * XPAD];
    __shared__ __half Wh[JM * WPAD];
    __shared__ __half Dst[B_ * DPAD];

    const int i = blockIdx.x;
    const int t = threadIdx.x;

    {
        int b = t >> 2, n0 = (t & 3) * 4;
        float4 x = *(const float4*)(inp + ((size_t)b * I_ + i) * N_ + n0);
        Xh[b * XPAD + n0 + 0] = __float2half_rn(x.x);
        Xh[b * XPAD + n0 + 1] = __float2half_rn(x.y);
        Xh[b * XPAD + n0 + 2] = __float2half_rn(x.z);
        Xh[b * XPAD + n0 + 3] = __float2half_rn(x.w);
    }
    {
        const float4* W4 = (const float4*)(W + (size_t)i * 4096);
        #pragma unroll
        for (int k = 0; k < 4; k++) {
            int e = t + k * 256;
            float4 w = W4[e];
            int idx = e * 4;
            int j = idx >> 8, n = (idx >> 4) & 15, m = idx & 15;
            int jm = j * 16 + m;
            Wh[(jm + 0) * WPAD + n] = __float2half_rn(w.x);
            Wh[(jm + 1) * WPAD + n] = __float2half_rn(w.y);
            Wh[(jm + 2) * WPAD + n] = __float2half_rn(w.z);
            Wh[(jm + 3) * WPAD + n] = __float2half_rn(w.w);
        }
    }
    __syncthreads();

    const int w = t >> 5, lane = t & 31;
    const int g = lane >> 2, q = lane & 3;

    uint32_t bf[4][2];
    #pragma unroll
    for (int f = 0; f < 4; f++) {
        int jm = (w * 4 + f) * 8 + g;
        bf[f][0] = *(const uint32_t*)&Wh[jm * WPAD + q * 2];
        bf[f][1] = *(const uint32_t*)&Wh[jm * WPAD + q * 2 + 8];
    }
    #pragma unroll
    for (int mt = 0; mt < 4; mt++) {
        int r0 = mt * 16 + g, r1 = r0 + 8;
        uint32_t a0 = *(const uint32_t*)&Xh[r0 * XPAD + q * 2];
        uint32_t a1 = *(const uint32_t*)&Xh[r1 * XPAD + q * 2];
        uint32_t a2 = *(const uint32_t*)&Xh[r0 * XPAD + q * 2 + 8];
        uint32_t a3 = *(const uint32_t*)&Xh[r1 * XPAD + q * 2 + 8];
        #pragma unroll
        for (int f = 0; f < 4; f++) {
            float d0 = 0.f, d1 = 0.f, d2 = 0.f, d3 = 0.f;
            asm volatile(
                "mma.sync.aligned.m16n8k16.row.col.f32.f16.f16.f32 "
                "{%0,%1,%2,%3}, {%4,%5,%6,%7}, {%8,%9}, {%0,%1,%2,%3};"
                : "+f"(d0), "+f"(d1), "+f"(d2), "+f"(d3)
                : "r"(a0), "r"(a1), "r"(a2), "r"(a3),
                  "r"(bf[f][0]), "r"(bf[f][1]));
            int jm = (w * 4 + f) * 8 + q * 2;
            *(__half2*)&Dst[r0 * DPAD + jm] = __floats2half2_rn(d0, d1);
            *(__half2*)&Dst[r1 * DPAD + jm] = __floats2half2_rn(d2, d3);
        }
    }
    __syncthreads();

    __half* up = g_uhat + (size_t)i * JM;
    #pragma unroll
    for (int k = 0; k < 8; k++) {
        int e = t + k * 256;
        int b = e >> 5, u = e & 31;
        uint4 v = *(const uint4*)&Dst[b * DPAD + u * 8];
        *(uint4*)(up + (size_t)b * (I_ * JM) + u * 8) = v;
    }
}

// ---------------------------------------------------------------------------
// K2 (fused persistent): all 3 routing iterations in one kernel.
// grid (B_, C_) = 512 CTAs; per-b pipelines gated by g_flag[b].
// __launch_bounds__(256,4): regs capped at 64 -> >=4 CTAs/SM -> 592 resident
// slots >= 512 CTAs (no spin deadlock).
__global__ void __launch_bounds__(256, 4) k_fused(float* __restrict__ out) {
    const int b    = blockIdx.x;
    const int wid  = threadIdx.x >> 5;
    const int lane = threadIdx.x & 31;
    const int t    = threadIdx.x;

    __shared__ float os[JM];
    __shared__ float ws[WPC][JM];
    __shared__ int   isLast;

    const int i0 = (blockIdx.y * WPC + wid) * IPW;
    const int4* base = (const int4*)(g_uhat + ((size_t)b * I_ + i0) * JM);
    const float L2E = 1.4426950408889634f;

    for (int phase = 0; phase < 3; phase++) {
        float o[8];
        if (phase) {
            os[t] = __ldcg(&g_osum[b * JM + t]) * L2E;   // bypass L1 (cross-SM)
            __syncthreads();
            #pragma unroll
            for (int k = 0; k < 8; k++) o[k] = os[lane * 8 + k];
        }

        float acc[8];
        #pragma unroll
        for (int k = 0; k < 8; k++) acc[k] = 0.f;

        for (int batch = 0; batch < IPW / 8; batch++) {
            int4 v[8];
            #pragma unroll
            for (int r = 0; r < 8; r++)
                v[r] = base[(batch * 8 + r) * (JM / 8) + lane];

            if (phase == 0) {
                // uniform c: plain sum (scaled by 1/16 at squash)
                #pragma unroll
                for (int r = 0; r < 8; r++) {
                    const __half2* hp = (const __half2*)&v[r];
                    #pragma unroll
                    for (int q = 0; q < 4; q++) {
                        float2 f = __half22float2(hp[q]);
                        acc[2 * q] += f.x; acc[2 * q + 1] += f.y;
                    }
                }
            } else {
                float p[8];
                #pragma unroll
                for (int r = 0; r < 8; r++) {
                    const __half2* hp = (const __half2*)&v[r];
                    float2 f0 = __half22float2(hp[0]), f1 = __half22float2(hp[1]);
                    float2 f2 = __half22float2(hp[2]), f3 = __half22float2(hp[3]);
                    p[r] = f0.x*o[0] + f0.y*o[1] + f1.x*o[2] + f1.y*o[3]
                         + f2.x*o[4] + f2.y*o[5] + f3.x*o[6] + f3.y*o[7];
                }
                #pragma unroll
                for (int r = 0; r < 8; r++)
                    p[r] += __shfl_xor_sync(0xffffffffu, p[r], 1);
                #pragma unroll
                for (int r = 0; r < 8; r++) p[r] = exp2f(p[r]);  // bounded fp32
                float sum[8];
                #pragma unroll
                for (int r = 0; r < 8; r++) sum[r] = p[r];
                #pragma unroll
                for (int off = 2; off < 32; off <<= 1) {
                    #pragma unroll
                    for (int r = 0; r < 8; r++)
                        sum[r] += __shfl_xor_sync(0xffffffffu, sum[r], off);
                }
                #pragma unroll
                for (int r = 0; r < 8; r++) {
                    float c = __fdividef(p[r], sum[r]);
                    const __half2* hp = (const __half2*)&v[r];
                    float2 f0 = __half22float2(hp[0]), f1 = __half22float2(hp[1]);
                    float2 f2 = __half22float2(hp[2]), f3 = __half22float2(hp[3]);
                    acc[0] += c * f0.x; acc[1] += c * f0.y;
                    acc[2] += c * f1.x; acc[3] += c * f1.y;
                    acc[4] += c * f2.x; acc[5] += c * f2.y;
                    acc[6] += c * f3.x; acc[7] += c * f3.y;
                }
            }
        }

        // per-warp stores + cross-warp tree + one global atomic per thread
        float* s_acc = g_scratch + phase * B_ * JM;
        {
            float4* dst = (float4*)&ws[wid][lane * 8];
            dst[0] = make_float4(acc[0], acc[1], acc[2], acc[3]);
            dst[1] = make_float4(acc[4], acc[5], acc[6], acc[7]);
            __syncthreads();
            float tsum = 0.f;
            #pragma unroll
            for (int w = 0; w < WPC; w++) tsum += ws[w][t];
            atomicAdd(&s_acc[b * JM + t], tsum);
        }

        // last CTA of this b finalizes: squash + osum/out + flag release
        __threadfence();
        if (t == 0)
            isLast = (atomicAdd(&g_counters[phase * B_ + b], 1) == C_ - 1);
        __syncthreads();
        if (isLast) {
            __threadfence();
            float s = *((volatile float*)&s_acc[b * JM + t]);
            if (phase == 0) s *= (1.f / 16.f);
            float n2 = s * s;
            #pragma unroll
            for (int off = 1; off < 16; off <<= 1)
                n2 += __shfl_xor_sync(0xffffffffu, n2, off);
            float v = n2 / (1.f + n2) * rsqrtf(n2 + 1e-8f) * s;
            if (phase == 2) out[b * JM + t] = v;
            else            atomicAdd(&g_osum[b * JM + t], v);
            __threadfence();
            __syncthreads();
            if (t == 0) atomicExch(&g_flag[b], phase + 1);
        }
        if (phase < 2) {
            if (t == 0) {
                while (atomicAdd(&g_flag[b], 0) <= phase) __nanosleep(64);
            }
            __syncthreads();
            __threadfence();
        }
    }
}

// ---------------------------------------------------------------------------
extern "C" void kernel_launch(void* const* d_in, const int* in_sizes, int n_in,
                              void* d_out, int out_size) {
    const float* inp = (const float*)d_in[0];   // [B, I, N]
    const float* W   = (const float*)d_in[1];   // [I, J, N, M]
    float* out = (float*)d_out;                 // [B, J, M]

    void *p_scr, *p_cnt, *p_os, *p_fl;
    cudaGetSymbolAddress(&p_scr, g_scratch);
    cudaGetSymbolAddress(&p_cnt, g_counters);
    cudaGetSymbolAddress(&p_os,  g_osum);
    cudaGetSymbolAddress(&p_fl,  g_flag);
    cudaMemsetAsync(p_scr, 0, 3 * B_ * JM * sizeof(float));
    cudaMemsetAsync(p_cnt, 0, 3 * B_ * sizeof(int));
    cudaMemsetAsync(p_os,  0, B_ * JM * sizeof(float));
    cudaMemsetAsync(p_fl,  0, B_ * sizeof(int));

    k_uhat<<<I_, 256>>>(inp, W);
    k_fused<<<dim3(B_, C_), 256>>>(out);        // all 3 routing iterations
}

// round 14
// speedup vs baseline: 1.6299x; 1.6299x over previous
#include <cuda_runtime.h>
#include <cuda_fp16.h>
#include <stdint.h>
#include <math.h>

// B=64, I=2048, N=16, J=16, M=16, 3 routing iters
#define B_  64
#define I_  2048
#define N_  16
#define J_  16
#define M_  16
#define JM  256
#define CHUNKS 16
#define WPC 8
#define IW (I_/(CHUNKS*WPC))   // = 16 i per warp per route pass

// Scratch (device globals). fp16 u_hat = 67 MB.
__device__ __half g_uhat[(size_t)B_ * I_ * JM];     // [b][i][j*16+m]
__device__ float  g_scratch[3 * B_ * JM];           // s0 | s1 | s2
__device__ float  g_osum[B_ * JM];
__device__ int    g_counters[3 * B_];

// ---------------------------------------------------------------------------
// K1 (HMMA): per CTA = one input capsule i.
//   D[b, jm] = X(64x16,f16) @ Wt(16x256,f16) via mma.sync m16n8k16 (fp32 acc)
#define XPAD 18
#define WPAD 18
#define DPAD 264
__global__ void __launch_bounds__(256) k_uhat(const float* __restrict__ inp,
                                              const float* __restrict__ W) {
    __shared__ __half Xh[B_ * XPAD];
    __shared__ __half Wh[JM * WPAD];
    __shared__ __half Dst[B_ * DPAD];

    const int i = blockIdx.x;
    const int t = threadIdx.x;

    {
        int b = t >> 2, n0 = (t & 3) * 4;
        float4 x = *(const float4*)(inp + ((size_t)b * I_ + i) * N_ + n0);
        Xh[b * XPAD + n0 + 0] = __float2half_rn(x.x);
        Xh[b * XPAD + n0 + 1] = __float2half_rn(x.y);
        Xh[b * XPAD + n0 + 2] = __float2half_rn(x.z);
        Xh[b * XPAD + n0 + 3] = __float2half_rn(x.w);
    }
    {
        const float4* W4 = (const float4*)(W + (size_t)i * 4096);
        #pragma unroll
        for (int k = 0; k < 4; k++) {
            int e = t + k * 256;
            float4 w = W4[e];
            int idx = e * 4;
            int j = idx >> 8, n = (idx >> 4) & 15, m = idx & 15;
            int jm = j * 16 + m;
            Wh[(jm + 0) * WPAD + n] = __float2half_rn(w.x);
            Wh[(jm + 1) * WPAD + n] = __float2half_rn(w.y);
            Wh[(jm + 2) * WPAD + n] = __float2half_rn(w.z);
            Wh[(jm + 3) * WPAD + n] = __float2half_rn(w.w);
        }
    }
    __syncthreads();

    const int w = t >> 5, lane = t & 31;
    const int g = lane >> 2, q = lane & 3;

    uint32_t bf[4][2];
    #pragma unroll
    for (int f = 0; f < 4; f++) {
        int jm = (w * 4 + f) * 8 + g;
        bf[f][0] = *(const uint32_t*)&Wh[jm * WPAD + q * 2];
        bf[f][1] = *(const uint32_t*)&Wh[jm * WPAD + q * 2 + 8];
    }
    #pragma unroll
    for (int mt = 0; mt < 4; mt++) {
        int r0 = mt * 16 + g, r1 = r0 + 8;
        uint32_t a0 = *(const uint32_t*)&Xh[r0 * XPAD + q * 2];
        uint32_t a1 = *(const uint32_t*)&Xh[r1 * XPAD + q * 2];
        uint32_t a2 = *(const uint32_t*)&Xh[r0 * XPAD + q * 2 + 8];
        uint32_t a3 = *(const uint32_t*)&Xh[r1 * XPAD + q * 2 + 8];
        #pragma unroll
        for (int f = 0; f < 4; f++) {
            float d0 = 0.f, d1 = 0.f, d2 = 0.f, d3 = 0.f;
            asm volatile(
                "mma.sync.aligned.m16n8k16.row.col.f32.f16.f16.f32 "
                "{%0,%1,%2,%3}, {%4,%5,%6,%7}, {%8,%9}, {%0,%1,%2,%3};"
                : "+f"(d0), "+f"(d1), "+f"(d2), "+f"(d3)
                : "r"(a0), "r"(a1), "r"(a2), "r"(a3),
                  "r"(bf[f][0]), "r"(bf[f][1]));
            int jm = (w * 4 + f) * 8 + q * 2;
            *(__half2*)&Dst[r0 * DPAD + jm] = __floats2half2_rn(d0, d1);
            *(__half2*)&Dst[r1 * DPAD + jm] = __floats2half2_rn(d2, d3);
        }
    }
    __syncthreads();

    __half* up = g_uhat + (size_t)i * JM;
    #pragma unroll
    for (int k = 0; k < 8; k++) {
        int e = t + k * 256;
        int b = e >> 5, u = e & 31;
        uint4 v = *(const uint4*)&Dst[b * DPAD + u * 8];
        *(uint4*)(up + (size_t)b * (I_ * JM) + u * 8) = v;
    }
}

// ---------------------------------------------------------------------------
// shared squash-update epilogue: last CTA of batch b finalizes the pass
__device__ __forceinline__ void squash_epilogue(int b, float* s_acc, int* cnt,
                                                float pre_scale, int final_pass,
                                                float* out, int ny) {
    __threadfence();
    __shared__ int isLast;
    if (threadIdx.x == 0)
        isLast = (atomicAdd(&cnt[b], 1) == ny - 1);
    __syncthreads();
    if (!isLast) return;
    __threadfence();

    float s = *((volatile float*)&s_acc[b * JM + threadIdx.x]) * pre_scale;
    float n2 = s * s;
    #pragma unroll
    for (int off = 1; off < 16; off <<= 1)
        n2 += __shfl_xor_sync(0xffffffffu, n2, off);
    float v = n2 / (1.f + n2) * rsqrtf(n2 + 1e-8f) * s;

    if (final_pass) out[b * JM + threadIdx.x] = v;
    else            atomicAdd(&g_osum[b * JM + threadIdx.x], v);
}

// per-warp plain stores + cross-warp tree reduce + one global atomic / thread
__device__ __forceinline__ void reduce_epilogue(int b, float* s_acc,
                                                float (&ws)[WPC][JM],
                                                const float* acc,
                                                int wid, int lane) {
    float4* dst = (float4*)&ws[wid][lane * 8];
    dst[0] = make_float4(acc[0], acc[1], acc[2], acc[3]);
    dst[1] = make_float4(acc[4], acc[5], acc[6], acc[7]);
    __syncthreads();
    float tsum = 0.f;
    #pragma unroll
    for (int w = 0; w < WPC; w++) tsum += ws[w][threadIdx.x];
    atomicAdd(&s_acc[b * JM + threadIdx.x], tsum);
}

// ---------------------------------------------------------------------------
// K2: iteration 0 = uniform-c reduction: s0 = (1/16) sum_i u_hat; squash fused.
__global__ void __launch_bounds__(256) k_red0() {
    const int b    = blockIdx.x;
    const int wid  = threadIdx.x >> 5;
    const int lane = threadIdx.x & 31;

    __shared__ float ws[WPC][JM];

    const int i0 = blockIdx.y * 128 + wid * 16;
    const int4* base = (const int4*)(g_uhat + ((size_t)b * I_ + i0) * JM);

    float acc[8];
    #pragma unroll
    for (int k = 0; k < 8; k++) acc[k] = 0.f;
    #pragma unroll
    for (int blk = 0; blk < 4; blk++) {
        int4 v[4];
        #pragma unroll
        for (int r = 0; r < 4; r++)
            v[r] = base[(blk * 4 + r) * (JM / 8) + lane];
        #pragma unroll
        for (int r = 0; r < 4; r++) {
            const __half2* hp = (const __half2*)&v[r];
            #pragma unroll
            for (int q = 0; q < 4; q++) {
                float2 f = __half22float2(hp[q]);
                acc[2 * q] += f.x; acc[2 * q + 1] += f.y;
            }
        }
    }
    reduce_epilogue(b, g_scratch, ws, acc, wid, lane);
    squash_epilogue(b, g_scratch, g_counters, 1.f / 16.f, 0, nullptr, gridDim.y);
}

// ---------------------------------------------------------------------------
// K3: routing pass (iters 1,2): lane l owns (j=l>>1, m-half l&1).
// 8-wide batched softmax; CORRECTED parity split: full p[0..7] computed and
// pair-combined first (both pair lanes then hold identical full logits),
// THEN even lane finishes rows 0..3 / odd lane rows 4..7 (exp/rcp/sum halved;
// butterfly offsets 2..16 preserve parity so each reduces over all 16 j).
// Partner's c recovered by one shfl fused directly into the accumulation.
__global__ void __launch_bounds__(256) k_route(float* __restrict__ s_acc,
                                               int* __restrict__ cnt,
                                               float* __restrict__ out,
                                               int final_pass) {
    const int b    = blockIdx.x;
    const int wid  = threadIdx.x >> 5;
    const int lane = threadIdx.x & 31;
    const bool odd = lane & 1;

    __shared__ float os[JM];
    __shared__ float ws[WPC][JM];
    os[threadIdx.x] = g_osum[b * JM + threadIdx.x];
    __syncthreads();

    const float L2E = 1.4426950408889634f;
    float o[8];
    #pragma unroll
    for (int k = 0; k < 8; k++) o[k] = os[lane * 8 + k] * L2E;

    float acc[8];
    #pragma unroll
    for (int k = 0; k < 8; k++) acc[k] = 0.f;

    const int i0 = (blockIdx.y * WPC + wid) * IW;
    const int4* base = (const int4*)(g_uhat + ((size_t)b * I_ + i0) * JM);

    #pragma unroll
    for (int batch = 0; batch < IW / 8; batch++) {
        int4 v[8];
        #pragma unroll
        for (int r = 0; r < 8; r++)
            v[r] = base[(batch * 8 + r) * (JM / 8) + lane];

        // full partial dots for ALL 8 rows (this lane's m-half), then combine
        float p[8];
        #pragma unroll
        for (int r = 0; r < 8; r++) {
            const __half2* hp = (const __half2*)&v[r];
            float2 f0 = __half22float2(hp[0]), f1 = __half22float2(hp[1]);
            float2 f2 = __half22float2(hp[2]), f3 = __half22float2(hp[3]);
            p[r] = f0.x*o[0] + f0.y*o[1] + f1.x*o[2] + f1.y*o[3]
                 + f2.x*o[4] + f2.y*o[5] + f3.x*o[6] + f3.y*o[7];
        }
        #pragma unroll
        for (int r = 0; r < 8; r++) p[r] += __shfl_xor_sync(0xffffffffu, p[r], 1);

        // parity split AFTER combine: this lane finishes 4 of the 8 rows
        float q[4];
        #pragma unroll
        for (int s = 0; s < 4; s++) q[s] = odd ? p[s + 4] : p[s];
        #pragma unroll
        for (int s = 0; s < 4; s++) q[s] = exp2f(q[s]);   // bounded fp32
        float sum[4];
        #pragma unroll
        for (int s = 0; s < 4; s++) sum[s] = q[s];
        #pragma unroll
        for (int off = 2; off < 32; off <<= 1) {          // parity-preserving
            #pragma unroll
            for (int s = 0; s < 4; s++)
                sum[s] += __shfl_xor_sync(0xffffffffu, sum[s], off);
        }
        #pragma unroll
        for (int s = 0; s < 4; s++) {
            float cm = __fdividef(q[s], sum[s]);          // c of row (odd? s+4 : s)
            float co = __shfl_xor_sync(0xffffffffu, cm, 1);
            float cA = odd ? co : cm;                     // c for row s
            float cB = odd ? cm : co;                     // c for row s+4
            {
                const __half2* hp = (const __half2*)&v[s];
                float2 f0 = __half22float2(hp[0]), f1 = __half22float2(hp[1]);
                float2 f2 = __half22float2(hp[2]), f3 = __half22float2(hp[3]);
                acc[0] += cA * f0.x; acc[1] += cA * f0.y;
                acc[2] += cA * f1.x; acc[3] += cA * f1.y;
                acc[4] += cA * f2.x; acc[5] += cA * f2.y;
                acc[6] += cA * f3.x; acc[7] += cA * f3.y;
            }
            {
                const __half2* hp = (const __half2*)&v[s + 4];
                float2 f0 = __half22float2(hp[0]), f1 = __half22float2(hp[1]);
                float2 f2 = __half22float2(hp[2]), f3 = __half22float2(hp[3]);
                acc[0] += cB * f0.x; acc[1] += cB * f0.y;
                acc[2] += cB * f1.x; acc[3] += cB * f1.y;
                acc[4] += cB * f2.x; acc[5] += cB * f2.y;
                acc[6] += cB * f3.x; acc[7] += cB * f3.y;
            }
        }
    }

    reduce_epilogue(b, s_acc, ws, acc, wid, lane);
    squash_epilogue(b, s_acc, cnt, 1.f, final_pass, out, gridDim.y);
}

// ---------------------------------------------------------------------------
extern "C" void kernel_launch(void* const* d_in, const int* in_sizes, int n_in,
                              void* d_out, int out_size) {
    const float* inp = (const float*)d_in[0];   // [B, I, N]
    const float* W   = (const float*)d_in[1];   // [I, J, N, M]
    float* out = (float*)d_out;                 // [B, J, M]

    void *p_scr, *p_cnt, *p_os;
    cudaGetSymbolAddress(&p_scr, g_scratch);
    cudaGetSymbolAddress(&p_cnt, g_counters);
    cudaGetSymbolAddress(&p_os,  g_osum);
    cudaMemsetAsync(p_scr, 0, 3 * B_ * JM * sizeof(float));
    cudaMemsetAsync(p_cnt, 0, 3 * B_ * sizeof(int));
    cudaMemsetAsync(p_os,  0, B_ * JM * sizeof(float));

    float* s1 = (float*)p_scr + B_ * JM;
    float* s2 = (float*)p_scr + 2 * B_ * JM;
    int* c1 = (int*)p_cnt + B_;
    int* c2 = (int*)p_cnt + 2 * B_;

    dim3 rg(B_, CHUNKS);
    k_uhat<<<I_, 256>>>(inp, W);
    k_red0<<<dim3(B_, 16), 256>>>();            // iter 0 (uniform c) + squash
    k_route<<<rg, 256>>>(s1, c1, out, 0);       // iter 1
    k_route<<<rg, 256>>>(s2, c2, out, 1);       // iter 2 -> d_out
}

// round 17
// speedup vs baseline: 1.6369x; 1.0043x over previous
#include <cuda_runtime.h>
#include <cuda_fp16.h>
#include <stdint.h>
#include <math.h>

// B=64, I=2048, N=16, J=16, M=16, 3 routing iters
#define B_  64
#define I_  2048
#define N_  16
#define J_  16
#define M_  16
#define JM  256
#define CHUNKS 16
#define WPC 8
#define IW (I_/(CHUNKS*WPC))   // = 16 i per warp per route pass

// Scratch (device globals). fp16 u_hat = 67 MB (pinned in L2 via evict_last).
__device__ __half g_uhat[(size_t)B_ * I_ * JM];     // [b][i][j*16+m]
__device__ float  g_scratch[3 * B_ * JM];           // s0 | s1 | s2
__device__ float  g_osum[B_ * JM];
__device__ int    g_counters[3 * B_];

// ---- L2 evict_last via createpolicy + cache_hint (sm_80+ portable form) ----
__device__ __forceinline__ uint64_t mk_evict_last_policy() {
    uint64_t pol;
    asm("createpolicy.fractional.L2::evict_last.b64 %0, 1.0;" : "=l"(pol));
    return pol;
}
__device__ __forceinline__ int4 ldg_el(const int4* p, uint64_t pol) {
    int4 v;
    asm volatile("ld.global.nc.L2::cache_hint.v4.u32 {%0,%1,%2,%3}, [%4], %5;"
                 : "=r"(v.x), "=r"(v.y), "=r"(v.z), "=r"(v.w)
                 : "l"(p), "l"(pol));
    return v;
}
__device__ __forceinline__ void stg_el(uint4* p, uint4 v, uint64_t pol) {
    asm volatile("st.global.L2::cache_hint.v4.u32 [%0], {%1,%2,%3,%4}, %5;"
                 :: "l"(p), "r"(v.x), "r"(v.y), "r"(v.z), "r"(v.w), "l"(pol)
                 : "memory");
}

// ---------------------------------------------------------------------------
// K1 (HMMA): per CTA = one input capsule i.
//   D[b, jm] = X(64x16,f16) @ Wt(16x256,f16) via mma.sync m16n8k16 (fp32 acc)
#define XPAD 18
#define WPAD 18
#define DPAD 264
__global__ void __launch_bounds__(256) k_uhat(const float* __restrict__ inp,
                                              const float* __restrict__ W) {
    __shared__ __half Xh[B_ * XPAD];
    __shared__ __half Wh[JM * WPAD];
    __shared__ __half Dst[B_ * DPAD];

    const int i = blockIdx.x;
    const int t = threadIdx.x;

    {
        int b = t >> 2, n0 = (t & 3) * 4;
        float4 x = *(const float4*)(inp + ((size_t)b * I_ + i) * N_ + n0);
        Xh[b * XPAD + n0 + 0] = __float2half_rn(x.x);
        Xh[b * XPAD + n0 + 1] = __float2half_rn(x.y);
        Xh[b * XPAD + n0 + 2] = __float2half_rn(x.z);
        Xh[b * XPAD + n0 + 3] = __float2half_rn(x.w);
    }
    {
        const float4* W4 = (const float4*)(W + (size_t)i * 4096);
        #pragma unroll
        for (int k = 0; k < 4; k++) {
            int e = t + k * 256;
            float4 w = W4[e];
            int idx = e * 4;
            int j = idx >> 8, n = (idx >> 4) & 15, m = idx & 15;
            int jm = j * 16 + m;
            Wh[(jm + 0) * WPAD + n] = __float2half_rn(w.x);
            Wh[(jm + 1) * WPAD + n] = __float2half_rn(w.y);
            Wh[(jm + 2) * WPAD + n] = __float2half_rn(w.z);
            Wh[(jm + 3) * WPAD + n] = __float2half_rn(w.w);
        }
    }
    __syncthreads();

    const int w = t >> 5, lane = t & 31;
    const int g = lane >> 2, q = lane & 3;

    uint32_t bf[4][2];
    #pragma unroll
    for (int f = 0; f < 4; f++) {
        int jm = (w * 4 + f) * 8 + g;
        bf[f][0] = *(const uint32_t*)&Wh[jm * WPAD + q * 2];
        bf[f][1] = *(const uint32_t*)&Wh[jm * WPAD + q * 2 + 8];
    }
    #pragma unroll
    for (int mt = 0; mt < 4; mt++) {
        int r0 = mt * 16 + g, r1 = r0 + 8;
        uint32_t a0 = *(const uint32_t*)&Xh[r0 * XPAD + q * 2];
        uint32_t a1 = *(const uint32_t*)&Xh[r1 * XPAD + q * 2];
        uint32_t a2 = *(const uint32_t*)&Xh[r0 * XPAD + q * 2 + 8];
        uint32_t a3 = *(const uint32_t*)&Xh[r1 * XPAD + q * 2 + 8];
        #pragma unroll
        for (int f = 0; f < 4; f++) {
            float d0 = 0.f, d1 = 0.f, d2 = 0.f, d3 = 0.f;
            asm volatile(
                "mma.sync.aligned.m16n8k16.row.col.f32.f16.f16.f32 "
                "{%0,%1,%2,%3}, {%4,%5,%6,%7}, {%8,%9}, {%0,%1,%2,%3};"
                : "+f"(d0), "+f"(d1), "+f"(d2), "+f"(d3)
                : "r"(a0), "r"(a1), "r"(a2), "r"(a3),
                  "r"(bf[f][0]), "r"(bf[f][1]));
            int jm = (w * 4 + f) * 8 + q * 2;
            *(__half2*)&Dst[r0 * DPAD + jm] = __floats2half2_rn(d0, d1);
            *(__half2*)&Dst[r1 * DPAD + jm] = __floats2half2_rn(d2, d3);
        }
    }
    __syncthreads();

    const uint64_t pol = mk_evict_last_policy();
    __half* up = g_uhat + (size_t)i * JM;
    #pragma unroll
    for (int k = 0; k < 8; k++) {
        int e = t + k * 256;
        int b = e >> 5, u = e & 31;
        uint4 v = *(const uint4*)&Dst[b * DPAD + u * 8];
        stg_el((uint4*)(up + (size_t)b * (I_ * JM) + u * 8), v, pol);
    }
}

// ---------------------------------------------------------------------------
// shared squash-update epilogue: last CTA of batch b finalizes the pass
__device__ __forceinline__ void squash_epilogue(int b, float* s_acc, int* cnt,
                                                float pre_scale, int final_pass,
                                                float* out, int ny) {
    __threadfence();
    __shared__ int isLast;
    if (threadIdx.x == 0)
        isLast = (atomicAdd(&cnt[b], 1) == ny - 1);
    __syncthreads();
    if (!isLast) return;
    __threadfence();

    float s = *((volatile float*)&s_acc[b * JM + threadIdx.x]) * pre_scale;
    float n2 = s * s;
    #pragma unroll
    for (int off = 1; off < 16; off <<= 1)
        n2 += __shfl_xor_sync(0xffffffffu, n2, off);
    float v = n2 / (1.f + n2) * rsqrtf(n2 + 1e-8f) * s;

    if (final_pass) out[b * JM + threadIdx.x] = v;
    else            atomicAdd(&g_osum[b * JM + threadIdx.x], v);
}

// per-warp plain stores + cross-warp tree reduce + one global atomic / thread
__device__ __forceinline__ void reduce_epilogue(int b, float* s_acc,
                                                float (&ws)[WPC][JM],
                                                const float* acc,
                                                int wid, int lane) {
    float4* dst = (float4*)&ws[wid][lane * 8];
    dst[0] = make_float4(acc[0], acc[1], acc[2], acc[3]);
    dst[1] = make_float4(acc[4], acc[5], acc[6], acc[7]);
    __syncthreads();
    float tsum = 0.f;
    #pragma unroll
    for (int w = 0; w < WPC; w++) tsum += ws[w][threadIdx.x];
    atomicAdd(&s_acc[b * JM + threadIdx.x], tsum);
}

// ---------------------------------------------------------------------------
// K2: iteration 0 = uniform-c reduction: s0 = (1/16) sum_i u_hat; squash fused.
__global__ void __launch_bounds__(256) k_red0() {
    const int b    = blockIdx.x;
    const int wid  = threadIdx.x >> 5;
    const int lane = threadIdx.x & 31;

    __shared__ float ws[WPC][JM];

    const int i0 = blockIdx.y * 128 + wid * 16;
    const int4* base = (const int4*)(g_uhat + ((size_t)b * I_ + i0) * JM);
    const uint64_t pol = mk_evict_last_policy();

    float acc[8];
    #pragma unroll
    for (int k = 0; k < 8; k++) acc[k] = 0.f;
    #pragma unroll
    for (int blk = 0; blk < 4; blk++) {
        int4 v[4];
        #pragma unroll
        for (int r = 0; r < 4; r++)
            v[r] = ldg_el(&base[(blk * 4 + r) * (JM / 8) + lane], pol);
        #pragma unroll
        for (int r = 0; r < 4; r++) {
            const __half2* hp = (const __half2*)&v[r];
            #pragma unroll
            for (int q = 0; q < 4; q++) {
                float2 f = __half22float2(hp[q]);
                acc[2 * q] += f.x; acc[2 * q + 1] += f.y;
            }
        }
    }
    reduce_epilogue(b, g_scratch, ws, acc, wid, lane);
    squash_epilogue(b, g_scratch, g_counters, 1.f / 16.f, 0, nullptr, gridDim.y);
}

// ---------------------------------------------------------------------------
// K3: routing pass (iters 1,2): lane l owns (j=l>>1, m-half l&1).
// 8-wide batched softmax with parity split (R14): full p[0..7] pair-combined,
// then even lane finishes rows 0..3 / odd lane rows 4..7; partner's c
// recovered by one shfl fused into the accumulation.
__global__ void __launch_bounds__(256) k_route(float* __restrict__ s_acc,
                                               int* __restrict__ cnt,
                                               float* __restrict__ out,
                                               int final_pass) {
    const int b    = blockIdx.x;
    const int wid  = threadIdx.x >> 5;
    const int lane = threadIdx.x & 31;
    const bool odd = lane & 1;

    __shared__ float os[JM];
    __shared__ float ws[WPC][JM];
    os[threadIdx.x] = g_osum[b * JM + threadIdx.x];
    __syncthreads();

    const float L2E = 1.4426950408889634f;
    float o[8];
    #pragma unroll
    for (int k = 0; k < 8; k++) o[k] = os[lane * 8 + k] * L2E;

    float acc[8];
    #pragma unroll
    for (int k = 0; k < 8; k++) acc[k] = 0.f;

    const int i0 = (blockIdx.y * WPC + wid) * IW;
    const int4* base = (const int4*)(g_uhat + ((size_t)b * I_ + i0) * JM);
    const uint64_t pol = mk_evict_last_policy();

    #pragma unroll
    for (int batch = 0; batch < IW / 8; batch++) {
        int4 v[8];
        #pragma unroll
        for (int r = 0; r < 8; r++)
            v[r] = ldg_el(&base[(batch * 8 + r) * (JM / 8) + lane], pol);

        float p[8];
        #pragma unroll
        for (int r = 0; r < 8; r++) {
            const __half2* hp = (const __half2*)&v[r];
            float2 f0 = __half22float2(hp[0]), f1 = __half22float2(hp[1]);
            float2 f2 = __half22float2(hp[2]), f3 = __half22float2(hp[3]);
            p[r] = f0.x*o[0] + f0.y*o[1] + f1.x*o[2] + f1.y*o[3]
                 + f2.x*o[4] + f2.y*o[5] + f3.x*o[6] + f3.y*o[7];
        }
        #pragma unroll
        for (int r = 0; r < 8; r++) p[r] += __shfl_xor_sync(0xffffffffu, p[r], 1);

        float q[4];
        #pragma unroll
        for (int s = 0; s < 4; s++) q[s] = odd ? p[s + 4] : p[s];
        #pragma unroll
        for (int s = 0; s < 4; s++) q[s] = exp2f(q[s]);   // bounded fp32
        float sum[4];
        #pragma unroll
        for (int s = 0; s < 4; s++) sum[s] = q[s];
        #pragma unroll
        for (int off = 2; off < 32; off <<= 1) {          // parity-preserving
            #pragma unroll
            for (int s = 0; s < 4; s++)
                sum[s] += __shfl_xor_sync(0xffffffffu, sum[s], off);
        }
        #pragma unroll
        for (int s = 0; s < 4; s++) {
            float cm = __fdividef(q[s], sum[s]);
            float co = __shfl_xor_sync(0xffffffffu, cm, 1);
            float cA = odd ? co : cm;
            float cB = odd ? cm : co;
            {
                const __half2* hp = (const __half2*)&v[s];
                float2 f0 = __half22float2(hp[0]), f1 = __half22float2(hp[1]);
                float2 f2 = __half22float2(hp[2]), f3 = __half22float2(hp[3]);
                acc[0] += cA * f0.x; acc[1] += cA * f0.y;
                acc[2] += cA * f1.x; acc[3] += cA * f1.y;
                acc[4] += cA * f2.x; acc[5] += cA * f2.y;
                acc[6] += cA * f3.x; acc[7] += cA * f3.y;
            }
            {
                const __half2* hp = (const __half2*)&v[s + 4];
                float2 f0 = __half22float2(hp[0]), f1 = __half22float2(hp[1]);
                float2 f2 = __half22float2(hp[2]), f3 = __half22float2(hp[3]);
                acc[0] += cB * f0.x; acc[1] += cB * f0.y;
                acc[2] += cB * f1.x; acc[3] += cB * f1.y;
                acc[4] += cB * f2.x; acc[5] += cB * f2.y;
                acc[6] += cB * f3.x; acc[7] += cB * f3.y;
            }
        }
    }

    reduce_epilogue(b, s_acc, ws, acc, wid, lane);
    squash_epilogue(b, s_acc, cnt, 1.f, final_pass, out, gridDim.y);
}

// ---------------------------------------------------------------------------
extern "C" void kernel_launch(void* const* d_in, const int* in_sizes, int n_in,
                              void* d_out, int out_size) {
    const float* inp = (const float*)d_in[0];   // [B, I, N]
    const float* W   = (const float*)d_in[1];   // [I, J, N, M]
    float* out = (float*)d_out;                 // [B, J, M]

    void *p_scr, *p_cnt, *p_os;
    cudaGetSymbolAddress(&p_scr, g_scratch);
    cudaGetSymbolAddress(&p_cnt, g_counters);
    cudaGetSymbolAddress(&p_os,  g_osum);
    cudaMemsetAsync(p_scr, 0, 3 * B_ * JM * sizeof(float));
    cudaMemsetAsync(p_cnt, 0, 3 * B_ * sizeof(int));
    cudaMemsetAsync(p_os,  0, B_ * JM * sizeof(float));

    float* s1 = (float*)p_scr + B_ * JM;
    float* s2 = (float*)p_scr + 2 * B_ * JM;
    int* c1 = (int*)p_cnt + B_;
    int* c2 = (int*)p_cnt + 2 * B_;

    dim3 rg(B_, CHUNKS);
    k_uhat<<<I_, 256>>>(inp, W);
    k_red0<<<dim3(B_, 16), 256>>>();            // iter 0 (uniform c) + squash
    k_route<<<rg, 256>>>(s1, c1, out, 0);       // iter 1
    k_route<<<rg, 256>>>(s2, c2, out, 1);       // iter 2 -> d_out
}